// round 2
// baseline (speedup 1.0000x reference)
#include <cuda_runtime.h>

#define B_  64
#define T_  2048
#define H_  128
#define N3  384
#define BT  (B_ * T_)

// Scratch (allocation-free rule: __device__ globals)
__device__ float g_gx  [ (size_t)BT * N3 ];   // pre-activations x@kernel+bias_in, per layer
__device__ float g_buf0[ (size_t)BT * H_ ];   // layer activations ping
__device__ float g_buf1[ (size_t)BT * H_ ];   // layer activations pong

// ---------------------------------------------------------------------------
// Numerics: overflow-safe fast sigmoid / tanh built on MUFU EX2 + RCP.
// exp argument is always <= 0 so no overflow; rel err ~1e-6, fine vs 1e-3.
// ---------------------------------------------------------------------------
__device__ __forceinline__ float fsigmoid(float x) {
    float e = __expf(-fabsf(x));               // in (0,1]
    float r = __fdividef(1.f, 1.f + e);
    return x >= 0.f ? r : 1.f - r;
}
__device__ __forceinline__ float ftanh(float x) {
    float e = __expf(-2.f * fabsf(x));         // in (0,1]
    float t = __fdividef(1.f - e, 1.f + e);
    return x >= 0.f ? t : -t;
}

// ---------------------------------------------------------------------------
// GEMM: C[M,N] = A[M,128] @ Bm[128,N] + bias[N]  (optional sigmoid epilogue)
// M = BT, N in {384, 128}. Tile: BM=64, BN=128, BK=32. 256 threads.
// sA stored [row][k] padded (+1) -> conflict-free scalar a-broadcast reads.
// sB stored [k][n] -> STS.128 / LDS.128.
// ---------------------------------------------------------------------------
__global__ void __launch_bounds__(256) gemm_bias(
    const float* __restrict__ A,
    const float* __restrict__ Bm,
    const float* __restrict__ bias,
    float*       __restrict__ C,
    int N, int applySigmoid)
{
    __shared__ float sA[64][33];
    __shared__ float sB[32][128];

    const int m0 = blockIdx.x * 64;
    const int n0 = blockIdx.y * 128;
    const int tid = threadIdx.x;
    const int tx = tid & 15;        // 16 col-groups, 8 cols each
    const int ty = tid >> 4;        // 16 row-groups, 4 rows each
    const int arow = tid >> 3;      // 0..31 (A loader)
    const int akq  = tid & 7;       // k-quad
    const int brow = tid >> 5;      // 0..7  (B loader)
    const int bcol = tid & 31;      // *4

    float acc[4][8];
    #pragma unroll
    for (int i = 0; i < 4; i++)
        #pragma unroll
        for (int j = 0; j < 8; j++) acc[i][j] = 0.f;

    for (int k0 = 0; k0 < 128; k0 += 32) {
        float4 a0 = *(const float4*)(A + (size_t)(m0 + arow     ) * H_ + k0 + akq * 4);
        float4 a1 = *(const float4*)(A + (size_t)(m0 + arow + 32) * H_ + k0 + akq * 4);
        float4 b0 = *(const float4*)(Bm + (size_t)(k0 + brow     ) * N + n0 + bcol * 4);
        float4 b1 = *(const float4*)(Bm + (size_t)(k0 + brow +  8) * N + n0 + bcol * 4);
        float4 b2 = *(const float4*)(Bm + (size_t)(k0 + brow + 16) * N + n0 + bcol * 4);
        float4 b3 = *(const float4*)(Bm + (size_t)(k0 + brow + 24) * N + n0 + bcol * 4);
        __syncthreads();   // previous tile fully consumed before overwrite
        sA[arow     ][akq * 4 + 0] = a0.x;  sA[arow     ][akq * 4 + 1] = a0.y;
        sA[arow     ][akq * 4 + 2] = a0.z;  sA[arow     ][akq * 4 + 3] = a0.w;
        sA[arow + 32][akq * 4 + 0] = a1.x;  sA[arow + 32][akq * 4 + 1] = a1.y;
        sA[arow + 32][akq * 4 + 2] = a1.z;  sA[arow + 32][akq * 4 + 3] = a1.w;
        *(float4*)&sB[brow     ][bcol * 4] = b0;
        *(float4*)&sB[brow +  8][bcol * 4] = b1;
        *(float4*)&sB[brow + 16][bcol * 4] = b2;
        *(float4*)&sB[brow + 24][bcol * 4] = b3;
        __syncthreads();

        #pragma unroll
        for (int k = 0; k < 32; k++) {
            float a[4];
            #pragma unroll
            for (int i = 0; i < 4; i++) a[i] = sA[ty * 4 + i][k];
            float4 bv0 = *(const float4*)&sB[k][tx * 8];
            float4 bv1 = *(const float4*)&sB[k][tx * 8 + 4];
            float bb[8] = {bv0.x, bv0.y, bv0.z, bv0.w, bv1.x, bv1.y, bv1.z, bv1.w};
            #pragma unroll
            for (int i = 0; i < 4; i++)
                #pragma unroll
                for (int j = 0; j < 8; j++)
                    acc[i][j] = fmaf(a[i], bb[j], acc[i][j]);
        }
    }

    float bs[8];
    #pragma unroll
    for (int j = 0; j < 8; j++) bs[j] = bias[n0 + tx * 8 + j];

    #pragma unroll
    for (int i = 0; i < 4; i++) {
        const int row = m0 + ty * 4 + i;
        float v[8];
        #pragma unroll
        for (int j = 0; j < 8; j++) {
            float x = acc[i][j] + bs[j];
            v[j] = applySigmoid ? fsigmoid(x) : x;
        }
        float4 o0 = {v[0], v[1], v[2], v[3]};
        float4 o1 = {v[4], v[5], v[6], v[7]};
        *(float4*)(C + (size_t)row * N + n0 + tx * 8    ) = o0;
        *(float4*)(C + (size_t)row * N + n0 + tx * 8 + 4) = o1;
    }
}

// ---------------------------------------------------------------------------
// GRU scan: one CTA per batch element, 384 threads (thread t owns column t of
// rec_kernel in 128 registers). Sequential over T. h lives in shared.
// gx already holds x@kernel + bias_in.
// ---------------------------------------------------------------------------
__global__ void __launch_bounds__(384, 1) gru_scan(
    const float* __restrict__ gx,     // [B, T, 384]
    const float* __restrict__ rec,    // [128, 384] row-major
    const float* __restrict__ brec_g, // [384]
    float*       __restrict__ y)      // [B, T, 128]
{
    const int b = blockIdx.x;
    const int t = threadIdx.x;        // 0..383 = output column

    float w[128];
    #pragma unroll
    for (int k = 0; k < 128; k++) w[k] = rec[k * N3 + t];   // coalesced
    const float brec = brec_g[t];

    __shared__ float h_s[H_];
    __shared__ float sgh[N3];
    __shared__ float sgx[N3];
    if (t < H_) h_s[t] = 0.f;
    __syncthreads();

    const float* gxp = gx + (size_t)b * T_ * N3 + t;
    float*       yp  = y  + (size_t)b * T_ * H_;

    for (int step = 0; step < T_; ++step) {
        // issue the gx load early; consumed ~800 cycles later
        float gxv = __ldg(gxp + (size_t)step * N3);

        // gh[t] = sum_k h[k] * rec[k][t]  (h4: LDS.128 broadcast)
        float acc0 = 0.f, acc1 = 0.f, acc2 = 0.f, acc3 = 0.f;
        #pragma unroll
        for (int k = 0; k < 128; k += 4) {
            float4 h4 = *(const float4*)&h_s[k];
            acc0 = fmaf(h4.x, w[k + 0], acc0);
            acc1 = fmaf(h4.y, w[k + 1], acc1);
            acc2 = fmaf(h4.z, w[k + 2], acc2);
            acc3 = fmaf(h4.w, w[k + 3], acc3);
        }
        sgh[t] = (acc0 + acc1) + (acc2 + acc3) + brec;
        sgx[t] = gxv;
        __syncthreads();

        if (t < H_) {
            float xz = sgx[t], xr = sgx[t + 128], xh = sgx[t + 256];
            float hz = sgh[t], hr = sgh[t + 128], hh = sgh[t + 256];
            float z    = fsigmoid(xz + hz);
            float r    = fsigmoid(xr + hr);
            float cand = ftanh(fmaf(r, hh, xh));
            float hn   = z * h_s[t] + (1.f - z) * cand;
            h_s[t] = hn;
            yp[(size_t)step * H_ + t] = hn;
        }
        __syncthreads();   // h_s visible + sgh/sgx consumed before next step
    }
}

// ---------------------------------------------------------------------------
extern "C" void kernel_launch(void* const* d_in, const int* in_sizes, int n_in,
                              void* d_out, int out_size)
{
    const float* X     = (const float*)d_in[0];   // [B,T,128]
    const float* kern  = (const float*)d_in[1];   // [128,384]
    const float* rec   = (const float*)d_in[2];   // [128,384]
    const float* b_in  = (const float*)d_in[3];   // [384]
    const float* b_rec = (const float*)d_in[4];   // [384]
    const float* W_out = (const float*)d_in[5];   // [128,128]
    const float* b_out = (const float*)d_in[6];   // [128]
    float* out = (float*)d_out;                   // [B,T,128]

    float *gx, *buf0, *buf1;
    cudaGetSymbolAddress((void**)&gx,   g_gx);
    cudaGetSymbolAddress((void**)&buf0, g_buf0);
    cudaGetSymbolAddress((void**)&buf1, g_buf1);

    dim3 gg(BT / 64, N3 / 128);   // (2048, 3)
    dim3 gf(BT / 64, 1);

    // Layer 1
    gemm_bias<<<gg, 256>>>(X,    kern, b_in, gx, N3, 0);
    gru_scan <<<B_, 384>>>(gx, rec, b_rec, buf0);
    // Layer 2
    gemm_bias<<<gg, 256>>>(buf0, kern, b_in, gx, N3, 0);
    gru_scan <<<B_, 384>>>(gx, rec, b_rec, buf1);
    // Layer 3
    gemm_bias<<<gg, 256>>>(buf1, kern, b_in, gx, N3, 0);
    gru_scan <<<B_, 384>>>(gx, rec, b_rec, buf0);
    // Output projection + sigmoid
    gemm_bias<<<gf, 256>>>(buf0, W_out, b_out, out, H_, 1);
}

// round 4
// speedup vs baseline: 1.0942x; 1.0942x over previous
#include <cuda_runtime.h>

#define B_  64
#define T_  2048
#define H_  128
#define N3  384
#define BT  (B_ * T_)

typedef unsigned long long ull;

// Scratch (allocation-free rule: __device__ globals)
__device__ float g_gx  [ (size_t)BT * N3 ];
__device__ float g_buf0[ (size_t)BT * H_ ];
__device__ float g_buf1[ (size_t)BT * H_ ];

// ---------------- packed f32x2 helpers (sm_103a FFMA2 path) ----------------
// pk2 / ffma2 / fadd2 / unpk2 operate purely on registers: safe as
// non-volatile asm (no memory access, CSE of identical register math is fine).
__device__ __forceinline__ ull pk2(float lo, float hi) {
    ull r; asm("mov.b64 %0,{%1,%2};" : "=l"(r) : "f"(lo), "f"(hi)); return r;
}
__device__ __forceinline__ ull ffma2(ull a, ull b, ull c) {
    ull d; asm("fma.rn.f32x2 %0,%1,%2,%3;" : "=l"(d) : "l"(a), "l"(b), "l"(c)); return d;
}
__device__ __forceinline__ ull fadd2(ull a, ull b) {
    ull d; asm("add.rn.f32x2 %0,%1,%2;" : "=l"(d) : "l"(a), "l"(b)); return d;
}
__device__ __forceinline__ void unpk2(ull v, float& lo, float& hi) {
    asm("mov.b64 {%0,%1},%2;" : "=f"(lo), "=f"(hi) : "l"(v));
}

// ---------------- numerics: overflow-safe fast sigmoid / tanh --------------
__device__ __forceinline__ float fsigmoid(float x) {
    float e = __expf(-fabsf(x));
    float r = __fdividef(1.f, 1.f + e);
    return x >= 0.f ? r : 1.f - r;
}
__device__ __forceinline__ float ftanh(float x) {
    float e = __expf(-2.f * fabsf(x));
    float t = __fdividef(1.f - e, 1.f + e);
    return x >= 0.f ? t : -t;
}

// ---------------------------------------------------------------------------
// GEMM: C[M,N] = A[M,128] @ Bm[128,N] + bias[N] (optional sigmoid epilogue)
// BM=64, BN=128, BK=32, 256 threads. Inner product via FFMA2.
// All shared loads are plain C++ float4 (ordered vs. __syncthreads).
// ---------------------------------------------------------------------------
__global__ void __launch_bounds__(256) gemm_bias(
    const float* __restrict__ A,
    const float* __restrict__ Bm,
    const float* __restrict__ bias,
    float*       __restrict__ C,
    int N, int applySigmoid)
{
    __shared__ float sA[64][33];
    __shared__ __align__(16) float sB[32][128];

    const int m0 = blockIdx.x * 64;
    const int n0 = blockIdx.y * 128;
    const int tid = threadIdx.x;
    const int tx = tid & 15;
    const int ty = tid >> 4;
    const int arow = tid >> 3;
    const int akq  = tid & 7;
    const int brow = tid >> 5;
    const int bcol = tid & 31;

    ull acc2[4][4];
    #pragma unroll
    for (int i = 0; i < 4; i++)
        #pragma unroll
        for (int j = 0; j < 4; j++) acc2[i][j] = 0ULL;

    for (int k0 = 0; k0 < 128; k0 += 32) {
        float4 a0 = *(const float4*)(A + (size_t)(m0 + arow     ) * H_ + k0 + akq * 4);
        float4 a1 = *(const float4*)(A + (size_t)(m0 + arow + 32) * H_ + k0 + akq * 4);
        float4 b0 = *(const float4*)(Bm + (size_t)(k0 + brow     ) * N + n0 + bcol * 4);
        float4 b1 = *(const float4*)(Bm + (size_t)(k0 + brow +  8) * N + n0 + bcol * 4);
        float4 b2 = *(const float4*)(Bm + (size_t)(k0 + brow + 16) * N + n0 + bcol * 4);
        float4 b3 = *(const float4*)(Bm + (size_t)(k0 + brow + 24) * N + n0 + bcol * 4);
        __syncthreads();
        sA[arow     ][akq * 4 + 0] = a0.x;  sA[arow     ][akq * 4 + 1] = a0.y;
        sA[arow     ][akq * 4 + 2] = a0.z;  sA[arow     ][akq * 4 + 3] = a0.w;
        sA[arow + 32][akq * 4 + 0] = a1.x;  sA[arow + 32][akq * 4 + 1] = a1.y;
        sA[arow + 32][akq * 4 + 2] = a1.z;  sA[arow + 32][akq * 4 + 3] = a1.w;
        *(float4*)&sB[brow     ][bcol * 4] = b0;
        *(float4*)&sB[brow +  8][bcol * 4] = b1;
        *(float4*)&sB[brow + 16][bcol * 4] = b2;
        *(float4*)&sB[brow + 24][bcol * 4] = b3;
        __syncthreads();

        #pragma unroll
        for (int k = 0; k < 32; k++) {
            ull pa[4];
            #pragma unroll
            for (int i = 0; i < 4; i++) {
                float a = sA[ty * 4 + i][k];
                pa[i] = pk2(a, a);
            }
            float4 bv0 = *(const float4*)&sB[k][tx * 8];
            float4 bv1 = *(const float4*)&sB[k][tx * 8 + 4];
            ull b01 = pk2(bv0.x, bv0.y);
            ull b23 = pk2(bv0.z, bv0.w);
            ull b45 = pk2(bv1.x, bv1.y);
            ull b67 = pk2(bv1.z, bv1.w);
            #pragma unroll
            for (int i = 0; i < 4; i++) {
                acc2[i][0] = ffma2(pa[i], b01, acc2[i][0]);
                acc2[i][1] = ffma2(pa[i], b23, acc2[i][1]);
                acc2[i][2] = ffma2(pa[i], b45, acc2[i][2]);
                acc2[i][3] = ffma2(pa[i], b67, acc2[i][3]);
            }
        }
    }

    float bs[8];
    #pragma unroll
    for (int j = 0; j < 8; j++) bs[j] = bias[n0 + tx * 8 + j];

    #pragma unroll
    for (int i = 0; i < 4; i++) {
        const int row = m0 + ty * 4 + i;
        float v[8];
        #pragma unroll
        for (int j = 0; j < 4; j++) unpk2(acc2[i][j], v[2 * j], v[2 * j + 1]);
        #pragma unroll
        for (int j = 0; j < 8; j++) {
            float x = v[j] + bs[j];
            v[j] = applySigmoid ? fsigmoid(x) : x;
        }
        float4 o0 = {v[0], v[1], v[2], v[3]};
        float4 o1 = {v[4], v[5], v[6], v[7]};
        *(float4*)(C + (size_t)row * N + n0 + tx * 8    ) = o0;
        *(float4*)(C + (size_t)row * N + n0 + tx * 8 + 4) = o1;
    }
}

// ---------------------------------------------------------------------------
// GRU scan: one CTA per batch, 384 threads. Thread t owns rec column t as
// 64 packed f32x2 registers; dot product via FFMA2 (384-cycle FMA floor).
// Thread t's own dot result IS hz/hr/hh for lane t&127, so z- and r-group
// sigmoids run locally and in parallel; h-group finishes after one barrier.
// h_s loads are plain float4 -> properly ordered vs. __syncthreads.
// ---------------------------------------------------------------------------
__global__ void __launch_bounds__(384, 1) gru_scan(
    const float* __restrict__ gx,     // [B, T, 384] = x@kernel + bias_in
    const float* __restrict__ rec,    // [128, 384]
    const float* __restrict__ brec_g, // [384]
    float*       __restrict__ y)      // [B, T, 128]
{
    const int b = blockIdx.x;
    const int t = threadIdx.x;
    const int role = t >> 7;          // 0=z, 1=r, 2=h
    const int i    = t & 127;

    ull w2[64];
    #pragma unroll
    for (int j = 0; j < 64; j++)
        w2[j] = pk2(rec[(2 * j) * N3 + t], rec[(2 * j + 1) * N3 + t]);
    const float brec = brec_g[t];

    __shared__ __align__(16) float h_s[H_];
    __shared__ float sz[H_];
    __shared__ float sr[H_];
    if (t < H_) h_s[t] = 0.f;
    __syncthreads();

    const float* gxp = gx + (size_t)b * T_ * N3 + t;
    float*       yp  = y  + (size_t)b * T_ * H_ + i;

    float gxv = __ldg(gxp);           // step 0, prefetched

    for (int step = 0; step < T_; ++step) {
        // prefetch next step's gx (~dot-product latency ahead of use)
        float gxn = 0.f;
        if (step + 1 < T_) gxn = __ldg(gxp + (size_t)(step + 1) * N3);

        // gh[t] = sum_k h[k] * rec[k][t]  -- packed FFMA2, LDS.128 broadcast
        ull a0 = 0ULL, a1 = 0ULL, a2 = 0ULL, a3 = 0ULL;
        #pragma unroll
        for (int q = 0; q < 16; q++) {
            float4 hA = *(const float4*)&h_s[q * 8];
            float4 hB = *(const float4*)&h_s[q * 8 + 4];
            a0 = ffma2(pk2(hA.x, hA.y), w2[4 * q + 0], a0);
            a1 = ffma2(pk2(hA.z, hA.w), w2[4 * q + 1], a1);
            a2 = ffma2(pk2(hB.x, hB.y), w2[4 * q + 2], a2);
            a3 = ffma2(pk2(hB.z, hB.w), w2[4 * q + 3], a3);
        }
        a0 = fadd2(fadd2(a0, a1), fadd2(a2, a3));
        float lo, hi;
        unpk2(a0, lo, hi);
        const float gh = lo + hi + brec;   // == hz (role 0) / hr (1) / hh (2)

        if (role == 0)      sz[i] = fsigmoid(gxv + gh);
        else if (role == 1) sr[i] = fsigmoid(gxv + gh);
        __syncthreads();

        if (role == 2) {
            float r    = sr[i];
            float z    = sz[i];
            float cand = ftanh(fmaf(r, gh, gxv));   // gxv == xh here
            float hn   = z * h_s[i] + (1.f - z) * cand;
            h_s[i] = hn;
            yp[(size_t)step * H_] = hn;
        }
        __syncthreads();   // h_s update visible before next dot

        gxv = gxn;
    }
}

// ---------------------------------------------------------------------------
extern "C" void kernel_launch(void* const* d_in, const int* in_sizes, int n_in,
                              void* d_out, int out_size)
{
    const float* X     = (const float*)d_in[0];
    const float* kern  = (const float*)d_in[1];
    const float* rec   = (const float*)d_in[2];
    const float* b_in  = (const float*)d_in[3];
    const float* b_rec = (const float*)d_in[4];
    const float* W_out = (const float*)d_in[5];
    const float* b_out = (const float*)d_in[6];
    float* out = (float*)d_out;

    float *gxs, *buf0, *buf1;
    cudaGetSymbolAddress((void**)&gxs,  g_gx);
    cudaGetSymbolAddress((void**)&buf0, g_buf0);
    cudaGetSymbolAddress((void**)&buf1, g_buf1);

    dim3 gg(BT / 64, N3 / 128);   // (2048, 3)
    dim3 gf(BT / 64, 1);

    gemm_bias<<<gg, 256>>>(X,    kern, b_in, gxs, N3, 0);
    gru_scan <<<B_, 384>>>(gxs, rec, b_rec, buf0);

    gemm_bias<<<gg, 256>>>(buf0, kern, b_in, gxs, N3, 0);
    gru_scan <<<B_, 384>>>(gxs, rec, b_rec, buf1);

    gemm_bias<<<gg, 256>>>(buf1, kern, b_in, gxs, N3, 0);
    gru_scan <<<B_, 384>>>(gxs, rec, b_rec, buf0);

    gemm_bias<<<gf, 256>>>(buf0, W_out, b_out, out, H_, 1);
}